// round 5
// baseline (speedup 1.0000x reference)
#include <cuda_runtime.h>
#include <math.h>

#define N3 (128*128*128)
#define NZH 65                       // Hermitian half length along z
#define KLINES (128*65)              // 8320 k-space lines for y/x passes

__device__ float2 d_kmesh[128*128*NZH];  // half-spectrum mesh (8.5 MB)
__device__ float  d_rho[N3];             // dense real mesh (8 MB)
__device__ float2 d_tw[128];             // tw[j] = exp(-2*pi*i*j/128)

// ---------------------------------------------------------------------------
__device__ __forceinline__ float2 cadd(float2 a, float2 b){ return make_float2(a.x+b.x, a.y+b.y); }
__device__ __forceinline__ float2 csub(float2 a, float2 b){ return make_float2(a.x-b.x, a.y-b.y); }
__device__ __forceinline__ float2 cmul(float2 a, float2 w){ return make_float2(a.x*w.x-a.y*w.y, a.x*w.y+a.y*w.x); }

__device__ __forceinline__ void inv3x3(const float* __restrict__ cell,
                                       float inv[9], float& det) {
    float a = __ldg(cell+0), b = __ldg(cell+1), c = __ldg(cell+2);
    float d = __ldg(cell+3), e = __ldg(cell+4), f = __ldg(cell+5);
    float g = __ldg(cell+6), h = __ldg(cell+7), i = __ldg(cell+8);
    float C00 =  (e*i - f*h), C01 = -(d*i - f*g), C02 =  (d*h - e*g);
    float C10 = -(b*i - c*h), C11 =  (a*i - c*g), C12 = -(a*h - b*g);
    float C20 =  (b*f - c*e), C21 = -(a*f - c*d), C22 =  (a*e - b*d);
    det = a*C00 + b*C01 + c*C02;
    float idet = 1.0f / det;
    inv[0]=C00*idet; inv[1]=C10*idet; inv[2]=C20*idet;
    inv[3]=C01*idet; inv[4]=C11*idet; inv[5]=C21*idet;
    inv[6]=C02*idet; inv[7]=C12*idet; inv[8]=C22*idet;
}

// ---------------------------------------------------------------------------
// zero mesh + write twiddle LUT
// ---------------------------------------------------------------------------
__global__ void k_zero() {
    int i = blockIdx.x * blockDim.x + threadIdx.x;   // 524288 float4s (8 MB)
    ((float4*)d_rho)[i] = make_float4(0.f, 0.f, 0.f, 0.f);
    if (blockIdx.x == 0 && threadIdx.x < 128) {
        float s, c;
        sincospif((float)threadIdx.x * (1.0f / 64.0f), &s, &c);
        d_tw[threadIdx.x] = make_float2(c, -s);
    }
}

// ---------------------------------------------------------------------------
// Warp-level 128-pt FFT. Input: r[n1] = x[n1*32 + lane].
// Output: r[k1] at lane p = X[k1 + 4*brev5(p)].
// CONJ=0: forward (e^{-i}), CONJ=1: inverse (e^{+i}, unnormalized).
// ---------------------------------------------------------------------------
template<int CONJ>
__device__ __forceinline__ void warp_fft128(float2 r[4], int lane) {
    // radix-4 DFT across registers (stride 32)
    {
        float2 t02 = cadd(r[0], r[2]), d02 = csub(r[0], r[2]);
        float2 t13 = cadd(r[1], r[3]), d13 = csub(r[1], r[3]);
        float2 jd = CONJ ? make_float2(-d13.y,  d13.x)
                         : make_float2( d13.y, -d13.x);
        r[0] = cadd(t02, t13);
        r[2] = csub(t02, t13);
        r[1] = cadd(d02, jd);
        r[3] = csub(d02, jd);
    }
    // twiddle W128^{lane*k1}
    {
        float2 w1 = __ldg(&d_tw[lane]);
        float2 w2 = __ldg(&d_tw[(2*lane) & 127]);
        float2 w3 = __ldg(&d_tw[(3*lane) & 127]);
        if (CONJ) { w1.y = -w1.y; w2.y = -w2.y; w3.y = -w3.y; }
        r[1] = cmul(r[1], w1);
        r[2] = cmul(r[2], w2);
        r[3] = cmul(r[3], w3);
    }
    // 5 DIF radix-2 stages across lanes via shfl.xor
    #pragma unroll
    for (int h = 16; h >= 1; h >>= 1) {
        float2 w = __ldg(&d_tw[(lane & (h - 1)) * (64 / h)]);
        if (CONJ) w.y = -w.y;
        bool upper = (lane & h) != 0;
        #pragma unroll
        for (int q = 0; q < 4; q++) {
            float2 o;
            o.x = __shfl_xor_sync(0xffffffffu, r[q].x, h);
            o.y = __shfl_xor_sync(0xffffffffu, r[q].y, h);
            r[q] = upper ? cmul(csub(o, r[q]), w) : cadd(r[q], o);
        }
    }
}

// ---------------------------------------------------------------------------
// z forward r2c (two-for-one): each warp packs 2 real lines into 1 complex
// line, FFTs in registers, Hermitian-unpacks via per-warp shared staging.
// 1024 blocks x 8 warps = 8192 packed lines = 16384 real lines. No barriers.
// ---------------------------------------------------------------------------
__global__ void k_fft_z_fwd() {
    __shared__ float2 sh[8 * 128];
    int tid = threadIdx.x, lane = tid & 31, w = tid >> 5;
    int gw = blockIdx.x * 8 + w;
    const float* rpA = d_rho + (2*gw) * 128;
    const float* rpB = rpA + 128;
    float2 r[4];
    #pragma unroll
    for (int n1 = 0; n1 < 4; n1++)
        r[n1] = make_float2(rpA[n1*32 + lane], rpB[n1*32 + lane]);
    warp_fft128<0>(r, lane);
    int bp = __brev(lane) >> 27;
    float2* C = sh + w * 128;
    #pragma unroll
    for (int k1 = 0; k1 < 4; k1++) C[k1 + 4*bp] = r[k1];
    __syncwarp();
    float2* oA = d_kmesh + (2*gw) * NZH;
    float2* oB = oA + NZH;
    #pragma unroll
    for (int t = 0; t < 2; t++) {
        int k = lane + 32*t;
        float2 Ck = C[k], Cm = C[(128 - k) & 127];
        oA[k] = make_float2(0.5f*(Ck.x + Cm.x),  0.5f*(Ck.y - Cm.y));
        oB[k] = make_float2(0.5f*(Ck.y + Cm.y), -0.5f*(Ck.x - Cm.x));
    }
    if (lane == 0) {
        float2 Ck = C[64];
        oA[64] = make_float2(Ck.x, 0.0f);
        oB[64] = make_float2(Ck.y, 0.0f);
    }
}

// ---------------------------------------------------------------------------
// z inverse c2r (two-for-one). No barriers.
// ---------------------------------------------------------------------------
__global__ void k_fft_z_inv() {
    __shared__ float2 sh[8 * 128];
    int tid = threadIdx.x, lane = tid & 31, w = tid >> 5;
    int gw = blockIdx.x * 8 + w;
    const float2* iA = d_kmesh + (2*gw) * NZH;
    const float2* iB = iA + NZH;
    float2* C = sh + w * 128;
    #pragma unroll
    for (int t = 0; t < 2; t++) {
        int k = lane + 32*t;                  // 0..63
        float2 A = iA[k], B = iB[k];
        C[k] = make_float2(A.x - B.y, A.y + B.x);
        if (k >= 1)
            C[128 - k] = make_float2(A.x + B.y, B.x - A.y);
    }
    if (lane == 0) {
        float2 A = iA[64], B = iB[64];
        C[64] = make_float2(A.x - B.y, A.y + B.x);
    }
    __syncwarp();
    float2 r[4];
    #pragma unroll
    for (int n1 = 0; n1 < 4; n1++) r[n1] = C[n1*32 + lane];
    warp_fft128<1>(r, lane);
    int bp = __brev(lane) >> 27;
    __syncwarp();
    #pragma unroll
    for (int k1 = 0; k1 < 4; k1++) C[k1 + 4*bp] = r[k1];
    __syncwarp();
    float* rpA = d_rho + (2*gw) * 128;
    float* rpB = rpA + 128;
    #pragma unroll
    for (int t = 0; t < 4; t++) {
        int n = lane + 32*t;
        float2 v = C[n];
        rpA[n] = v.x;
        rpB[n] = v.y;
    }
}

// ---------------------------------------------------------------------------
// y pass (stride NZH): block stages 8 lines through shared for coalescing,
// each warp FFTs one line in registers. 1040 blocks.
// ---------------------------------------------------------------------------
template<int CONJ>
__global__ void k_fft_y() {
    __shared__ float2 sh[8 * 129];
    __shared__ int lineBase[8];
    int tid = threadIdx.x, lane = tid & 31, w = tid >> 5;
    if (tid < 8) {
        int L = blockIdx.x * 8 + tid;
        int x = L / NZH, kz = L - x * NZH;
        lineBase[tid] = x * (128 * NZH) + kz;
    }
    __syncthreads();
    #pragma unroll
    for (int e = tid; e < 1024; e += 256) {
        int c = e & 7, l = e >> 3;
        sh[c * 129 + l] = d_kmesh[lineBase[c] + l * NZH];
    }
    __syncthreads();
    float2 r[4];
    #pragma unroll
    for (int n1 = 0; n1 < 4; n1++) r[n1] = sh[w * 129 + n1*32 + lane];
    warp_fft128<CONJ>(r, lane);
    int bp = __brev(lane) >> 27;
    __syncwarp();
    #pragma unroll
    for (int k1 = 0; k1 < 4; k1++) sh[w * 129 + k1 + 4*bp] = r[k1];
    __syncthreads();
    #pragma unroll
    for (int e = tid; e < 1024; e += 256) {
        int c = e & 7, l = e >> 3;
        d_kmesh[lineBase[c] + l * NZH] = sh[c * 129 + l];
    }
}

// ---------------------------------------------------------------------------
// Fused x pass: fwd FFT, G(k)/V in registers, inv FFT. 1040 blocks.
// lines L = y*65 + kz, elements at x*8320 + L.
// ---------------------------------------------------------------------------
__global__ void k_fft_x_gmul(const float* __restrict__ cell) {
    __shared__ float2 sh[8 * 129];
    int tid = threadIdx.x, lane = tid & 31, w = tid >> 5;
    int L0 = blockIdx.x * 8;
    // reciprocal basis + 1/V per thread (cheap, removes setup kernel)
    float inv[9]; float det;
    inv3x3(cell, inv, det);
    const float TWO_PI = 6.283185307179586f;
    float b0x = TWO_PI*inv[0], b0y = TWO_PI*inv[3], b0z = TWO_PI*inv[6];
    float b1x = TWO_PI*inv[1], b1y = TWO_PI*inv[4], b1z = TWO_PI*inv[7];
    float b2x = TWO_PI*inv[2], b2y = TWO_PI*inv[5], b2z = TWO_PI*inv[8];
    float ivol = 1.0f / fabsf(det);
    int L = L0 + w;
    int yy = L / NZH, kz = L - yy * NZH;
    float mj = (float)(yy - ((yy >= 64) ? 128 : 0));
    float mk = (float)kz;

    #pragma unroll
    for (int e = tid; e < 1024; e += 256) {
        int c = e & 7, l = e >> 3;
        sh[c * 129 + l] = d_kmesh[L0 + c + l * KLINES];
    }
    __syncthreads();
    float2 r[4];
    #pragma unroll
    for (int n1 = 0; n1 < 4; n1++) r[n1] = sh[w * 129 + n1*32 + lane];
    warp_fft128<0>(r, lane);
    int bp = __brev(lane) >> 27;
    // G(k)/V directly in registers: r[k1] holds X[k1 + 4*bp]
    #pragma unroll
    for (int k1 = 0; k1 < 4; k1++) {
        int kxi = k1 + 4*bp;
        float mi = (float)(kxi - ((kxi >= 64) ? 128 : 0));
        float kx = mi * b0x + mj * b1x + mk * b2x;
        float ky = mi * b0y + mj * b1y + mk * b2y;
        float kzv = mi * b0z + mj * b1z + mk * b2z;
        float ksq = kx*kx + ky*ky + kzv*kzv;
        float g = 0.0f;
        if (ksq != 0.0f)
            g = 12.566370614359172f / ksq * expf(-0.5f * ksq) * ivol;
        r[k1].x *= g; r[k1].y *= g;
    }
    // reorder to natural order for inverse FFT input
    __syncwarp();
    #pragma unroll
    for (int k1 = 0; k1 < 4; k1++) sh[w * 129 + k1 + 4*bp] = r[k1];
    __syncwarp();
    #pragma unroll
    for (int n1 = 0; n1 < 4; n1++) r[n1] = sh[w * 129 + n1*32 + lane];
    warp_fft128<1>(r, lane);
    __syncwarp();
    #pragma unroll
    for (int k1 = 0; k1 < 4; k1++) sh[w * 129 + k1 + 4*bp] = r[k1];
    __syncthreads();
    #pragma unroll
    for (int e = tid; e < 1024; e += 256) {
        int c = e & 7, l = e >> 3;
        d_kmesh[L0 + c + l * KLINES] = sh[c * 129 + l];
    }
}

// ---------------------------------------------------------------------------
// spline weights + stencil
// ---------------------------------------------------------------------------
__device__ __forceinline__ void spline_w4(float x, float* w) {
    float x2 = x * x, x3 = x2 * x;
    const float s = 1.0f / 48.0f;
    w[0] = ( 1.0f -  6.0f*x + 12.0f*x2 -  8.0f*x3) * s;
    w[1] = (23.0f - 30.0f*x - 12.0f*x2 + 24.0f*x3) * s;
    w[2] = (23.0f + 30.0f*x - 12.0f*x2 - 24.0f*x3) * s;
    w[3] = ( 1.0f +  6.0f*x + 12.0f*x2 +  8.0f*x3) * s;
}

__device__ __forceinline__ int atom_stencil(
    const float* __restrict__ cell, const float* __restrict__ pos, int a,
    float* wx, float* wy, float* wz, int* ix, int* iy)
{
    float inv[9]; float det;
    inv3x3(cell, inv, det);
    float p0 = pos[3*a], p1 = pos[3*a+1], p2 = pos[3*a+2];
    float r0 = (p0*inv[0] + p1*inv[3] + p2*inv[6]) * 128.0f;
    float r1 = (p0*inv[1] + p1*inv[4] + p2*inv[7]) * 128.0f;
    float r2 = (p0*inv[2] + p1*inv[5] + p2*inv[8]) * 128.0f;
    int i0 = __float2int_rd(r0);
    int i1 = __float2int_rd(r1);
    int i2 = __float2int_rd(r2);
    spline_w4(r0 - (float)i0 - 0.5f, wx);
    spline_w4(r1 - (float)i1 - 0.5f, wy);
    spline_w4(r2 - (float)i2 - 0.5f, wz);
    #pragma unroll
    for (int s = 0; s < 4; s++) {
        ix[s] = (i0 + s - 1 + 128) & 127;
        iy[s] = (i1 + s - 1 + 128) & 127;
    }
    return i2;
}

__device__ __forceinline__ void pad_quads(const float* wz, int off,
                                          float* q0, float* q1) {
    switch (off) {
    case 0: q0[0]=wz[0]; q0[1]=wz[1]; q0[2]=wz[2]; q0[3]=wz[3]; break;
    case 1: q0[1]=wz[0]; q0[2]=wz[1]; q0[3]=wz[2]; q1[0]=wz[3]; break;
    case 2: q0[2]=wz[0]; q0[3]=wz[1]; q1[0]=wz[2]; q1[1]=wz[3]; break;
    default:q0[3]=wz[0]; q1[0]=wz[1]; q1[1]=wz[2]; q1[2]=wz[3]; break;
    }
}

__device__ __forceinline__ void red4(float* p, float a, float b, float c, float d) {
    asm volatile("red.global.add.v4.f32 [%0], {%1, %2, %3, %4};"
                 :: "l"(p), "f"(a), "f"(b), "f"(c), "f"(d) : "memory");
}
__device__ __forceinline__ void red2(float* p, float a, float b) {
    asm volatile("red.global.add.v2.f32 [%0], {%1, %2};"
                 :: "l"(p), "f"(a), "f"(b) : "memory");
}
__device__ __forceinline__ void red1(float* p, float a) {
    asm volatile("red.global.add.f32 [%0], %1;"
                 :: "l"(p), "f"(a) : "memory");
}

// ---------------------------------------------------------------------------
__global__ void k_scatter(const float* __restrict__ cell,
                          const float* __restrict__ pos,
                          const float* __restrict__ chg, int n) {
    int a = blockIdx.x * blockDim.x + threadIdx.x;
    if (a >= n) return;
    float wx[4], wy[4], wz[4];
    int ix[4], iy[4];
    int i2 = atom_stencil(cell, pos, a, wx, wy, wz, ix, iy);
    float c = chg[a];
    int zlo = i2 - 1;
    if (zlo >= 0 && zlo <= 124) {
        int Q0 = zlo & ~3, off = zlo & 3;
        #pragma unroll
        for (int i = 0; i < 4; i++) {
            float cwi = c * wx[i];
            int ox = ix[i] << 14;
            #pragma unroll
            for (int j = 0; j < 4; j++) {
                float s = cwi * wy[j];
                float* p = &d_rho[ox + (iy[j] << 7) + Q0];
                switch (off) {
                case 0:
                    red4(p, s*wz[0], s*wz[1], s*wz[2], s*wz[3]);
                    break;
                case 1:
                    red1(p + 1, s*wz[0]);
                    red2(p + 2, s*wz[1], s*wz[2]);
                    red1(p + 4, s*wz[3]);
                    break;
                case 2:
                    red2(p + 2, s*wz[0], s*wz[1]);
                    red2(p + 4, s*wz[2], s*wz[3]);
                    break;
                default:
                    red1(p + 3, s*wz[0]);
                    red2(p + 4, s*wz[1], s*wz[2]);
                    red1(p + 6, s*wz[3]);
                    break;
                }
            }
        }
    } else {
        int iz[4];
        #pragma unroll
        for (int s = 0; s < 4; s++) iz[s] = (zlo + s + 128) & 127;
        #pragma unroll
        for (int i = 0; i < 4; i++) {
            float cwi = c * wx[i];
            int ox = ix[i] << 14;
            #pragma unroll
            for (int j = 0; j < 4; j++) {
                float cwij = cwi * wy[j];
                int oxy = ox + (iy[j] << 7);
                #pragma unroll
                for (int k = 0; k < 4; k++)
                    red1(&d_rho[oxy + iz[k]], cwij * wz[k]);
            }
        }
    }
}

// ---------------------------------------------------------------------------
__global__ void k_gather(const float* __restrict__ cell,
                         const float* __restrict__ pos,
                         const float* __restrict__ chg,
                         float* __restrict__ out, int n) {
    int a = blockIdx.x * blockDim.x + threadIdx.x;
    if (a >= n) return;
    float wx[4], wy[4], wz[4];
    int ix[4], iy[4];
    int i2 = atom_stencil(cell, pos, a, wx, wy, wz, ix, iy);
    float sum = 0.0f;
    int zlo = i2 - 1;
    if (zlo >= 0 && zlo <= 124) {
        int Q0 = zlo & ~3, off = zlo & 3;
        float q0[4] = {0,0,0,0}, q1[4] = {0,0,0,0};
        pad_quads(wz, off, q0, q1);
        #pragma unroll
        for (int i = 0; i < 4; i++) {
            float wi = wx[i];
            int ox = ix[i] << 14;
            #pragma unroll
            for (int j = 0; j < 4; j++) {
                const float* p = &d_rho[ox + (iy[j] << 7) + Q0];
                float4 v0 = __ldg((const float4*)p);
                float acc = v0.x*q0[0] + v0.y*q0[1] + v0.z*q0[2] + v0.w*q0[3];
                if (off) {
                    float4 v1 = __ldg((const float4*)(p + 4));
                    acc += v1.x*q1[0] + v1.y*q1[1] + v1.z*q1[2] + v1.w*q1[3];
                }
                sum += wi * wy[j] * acc;
            }
        }
    } else {
        int iz[4];
        #pragma unroll
        for (int s = 0; s < 4; s++) iz[s] = (zlo + s + 128) & 127;
        #pragma unroll
        for (int i = 0; i < 4; i++) {
            float wi = wx[i];
            int ox = ix[i] << 14;
            #pragma unroll
            for (int j = 0; j < 4; j++) {
                int oxy = ox + (iy[j] << 7);
                float acc = 0.0f;
                #pragma unroll
                for (int k = 0; k < 4; k++)
                    acc += wz[k] * d_rho[oxy + iz[k]];
                sum += wi * wy[j] * acc;
            }
        }
    }
    out[a] = sum - chg[a] * 0.7978845608028654f;
}

// ---------------------------------------------------------------------------
extern "C" void kernel_launch(void* const* d_in, const int* in_sizes, int n_in,
                              void* d_out, int out_size) {
    const float* cell = (const float*)d_in[0];
    const float* pos  = (const float*)d_in[1];
    const float* chg  = (const float*)d_in[2];
    float* out = (float*)d_out;
    int n = in_sizes[2];

    k_zero<<<2048, 256>>>();

    int ab = (n + 255) / 256;
    k_scatter<<<ab, 256>>>(cell, pos, chg, n);

    k_fft_z_fwd<<<1024, 256>>>();
    k_fft_y<0><<<1040, 256>>>();
    k_fft_x_gmul<<<1040, 256>>>(cell);
    k_fft_y<1><<<1040, 256>>>();
    k_fft_z_inv<<<1024, 256>>>();

    k_gather<<<ab, 256>>>(cell, pos, chg, out, n);
}

// round 6
// speedup vs baseline: 1.0299x; 1.0299x over previous
#include <cuda_runtime.h>
#include <math.h>

#define N3 (128*128*128)
#define NZH 65                       // Hermitian half length along z
#define KLINES (128*65)              // 8320 k-space lines for y/x passes

__device__ float2 d_kmesh[128*128*NZH];  // half-spectrum mesh (8.5 MB)
__device__ float  d_rho[N3];             // dense real mesh (8 MB)

// ---------------------------------------------------------------------------
__device__ __forceinline__ float2 cadd(float2 a, float2 b){ return make_float2(a.x+b.x, a.y+b.y); }
__device__ __forceinline__ float2 csub(float2 a, float2 b){ return make_float2(a.x-b.x, a.y-b.y); }
__device__ __forceinline__ float2 cmul(float2 a, float2 w){ return make_float2(a.x*w.x-a.y*w.y, a.x*w.y+a.y*w.x); }

// XOR bank swizzle: kills the 8-way conflicts of strided Stockham stores
// while leaving lane-consecutive accesses conflict-free.
__device__ __forceinline__ int sw(int i) { return i ^ (((i >> 5) & 3) << 2); }

__device__ __forceinline__ void inv3x3(const float* __restrict__ cell,
                                       float inv[9], float& det) {
    float a = __ldg(cell+0), b = __ldg(cell+1), c = __ldg(cell+2);
    float d = __ldg(cell+3), e = __ldg(cell+4), f = __ldg(cell+5);
    float g = __ldg(cell+6), h = __ldg(cell+7), i = __ldg(cell+8);
    float C00 =  (e*i - f*h), C01 = -(d*i - f*g), C02 =  (d*h - e*g);
    float C10 = -(b*i - c*h), C11 =  (a*i - c*g), C12 = -(a*h - b*g);
    float C20 =  (b*f - c*e), C21 = -(a*f - c*d), C22 =  (a*e - b*d);
    det = a*C00 + b*C01 + c*C02;
    float idet = 1.0f / det;
    inv[0]=C00*idet; inv[1]=C10*idet; inv[2]=C20*idet;
    inv[3]=C01*idet; inv[4]=C11*idet; inv[5]=C21*idet;
    inv[6]=C02*idet; inv[7]=C12*idet; inv[8]=C22*idet;
}

__global__ void k_zero() {
    int i = blockIdx.x * blockDim.x + threadIdx.x;   // 524288 float4s (8 MB)
    ((float4*)d_rho)[i] = make_float4(0.f, 0.f, 0.f, 0.f);
}

// ---------------------------------------------------------------------------
// Radix-4 Stockham stage over 8 lines of 128 (padded stride 129, swizzled).
// 8 lines * 32 butterflies = 256 items = 1 per thread.
// ---------------------------------------------------------------------------
template<int CONJ, int S>
__device__ __forceinline__ void r4_stage(const float2* __restrict__ cur,
                                         float2* __restrict__ nxt,
                                         const float2* __restrict__ tw, int tid) {
    int c = tid >> 5, t = tid & 31;
    int off = c * 129;
    int q  = t & (S - 1);
    int sp = t - q;
    float2 a0 = cur[sw(off + t)];
    float2 a1 = cur[sw(off + t + 32)];
    float2 a2 = cur[sw(off + t + 64)];
    float2 a3 = cur[sw(off + t + 96)];
    float2 t02 = cadd(a0, a2), d02 = csub(a0, a2);
    float2 t13 = cadd(a1, a3), d13 = csub(a1, a3);
    float2 y0 = cadd(t02, t13);
    float2 y2 = csub(t02, t13);
    float2 jd;
    if (CONJ) jd = make_float2(-d13.y,  d13.x);
    else      jd = make_float2( d13.y, -d13.x);
    float2 y1 = cadd(d02, jd);
    float2 y3 = csub(d02, jd);
    float2 w1 = tw[sp], w2 = tw[2*sp], w3 = tw[3*sp];
    if (CONJ) { w1.y = -w1.y; w2.y = -w2.y; w3.y = -w3.y; }
    int o = off + t + 3*sp;
    nxt[sw(o)]       = y0;
    nxt[sw(o + S)]   = cmul(y1, w1);
    nxt[sw(o + 2*S)] = cmul(y2, w2);
    nxt[sw(o + 3*S)] = cmul(y3, w3);
}

template<int CONJ>
__device__ __forceinline__ void fft_r4_stages(float2* A, float2* B,
                                              const float2* tw, int tid) {
    r4_stage<CONJ, 1 >(A, B, tw, tid); __syncthreads();
    r4_stage<CONJ, 4 >(B, A, tw, tid); __syncthreads();
    r4_stage<CONJ, 16>(A, B, tw, tid); __syncthreads();
    // result (pre final radix-2) in B
}

// twiddle-free final radix-2: 8 lines * 64 = 512 items
__device__ __forceinline__ void r2_final_shared(const float2* __restrict__ src,
                                                float2* __restrict__ dst, int tid) {
    #pragma unroll
    for (int e = tid; e < 512; e += 256) {
        int c = e >> 6, t = e & 63;
        float2 a = src[sw(c * 129 + t)], b = src[sw(c * 129 + t + 64)];
        dst[sw(c * 129 + t)]      = cadd(a, b);
        dst[sw(c * 129 + t + 64)] = csub(a, b);
    }
}

__device__ __forceinline__ void init_tw(float2* tw, int tid) {
    if (tid < 128) {
        float s, c;
        sincospif((float)tid * (1.0f / 64.0f), &s, &c);
        tw[tid] = make_float2(c, -s);
    }
}

// ---------------------------------------------------------------------------
// z forward r2c (two-for-one): 16 real lines -> 16 half-spectrum lines / block
// 1024 blocks
// ---------------------------------------------------------------------------
__global__ void k_fft_z_fwd() {
    __shared__ float2 bufA[8 * 129];
    __shared__ float2 bufB[8 * 129];
    __shared__ float2 tw[128];
    int tid = threadIdx.x;
    int rl0 = blockIdx.x * 16;                 // first real line
    init_tw(tw, tid);
    const float* rp = d_rho + rl0 * 128;
    #pragma unroll
    for (int e = tid; e < 1024; e += 256) {
        int c = e >> 7, l = e & 127;
        bufA[sw(c * 129 + l)] = make_float2(rp[(2*c) * 128 + l], rp[(2*c+1) * 128 + l]);
    }
    __syncthreads();
    fft_r4_stages<0>(bufA, bufB, tw, tid);
    r2_final_shared(bufB, bufA, tid);
    __syncthreads();
    // unpack: real line (rl0+2c) -> A_k, (rl0+2c+1) -> B_k
    for (int e = tid; e < 16 * NZH; e += 256) {
        int rl = e / NZH, k = e - rl * NZH;
        int c = rl >> 1;
        float2 Ck = bufA[sw(c * 129 + k)];
        float2 Cm = bufA[sw(c * 129 + ((128 - k) & 127))];
        float2 v;
        if ((rl & 1) == 0)
            v = make_float2(0.5f * (Ck.x + Cm.x), 0.5f * (Ck.y - Cm.y));
        else
            v = make_float2(0.5f * (Ck.y + Cm.y), -0.5f * (Ck.x - Cm.x));
        d_kmesh[(rl0 + rl) * NZH + k] = v;
    }
}

// ---------------------------------------------------------------------------
// z inverse c2r (two-for-one): 16 half-spectrum lines -> 16 real lines / block
// 1024 blocks
// ---------------------------------------------------------------------------
__global__ void k_fft_z_inv() {
    __shared__ float2 bufA[8 * 129];
    __shared__ float2 bufB[8 * 129];
    __shared__ float2 tw[128];
    int tid = threadIdx.x;
    int rl0 = blockIdx.x * 16;
    init_tw(tw, tid);
    for (int e = tid; e < 8 * NZH; e += 256) {
        int c = e / NZH, k = e - c * NZH;
        float2 A = d_kmesh[(rl0 + 2*c)   * NZH + k];
        float2 B = d_kmesh[(rl0 + 2*c+1) * NZH + k];
        bufA[sw(c * 129 + k)] = make_float2(A.x - B.y, A.y + B.x);
        if (k >= 1 && k <= 63)
            bufA[sw(c * 129 + 128 - k)] = make_float2(A.x + B.y, B.x - A.y);
    }
    __syncthreads();
    fft_r4_stages<1>(bufA, bufB, tw, tid);
    float* rp = d_rho + rl0 * 128;
    #pragma unroll
    for (int e = tid; e < 512; e += 256) {
        int c = e >> 6, l = e & 63;
        float2 a = bufB[sw(c * 129 + l)], b = bufB[sw(c * 129 + l + 64)];
        float2 su = cadd(a, b), df = csub(a, b);
        rp[(2*c) * 128 + l]        = su.x;
        rp[(2*c+1) * 128 + l]      = su.y;
        rp[(2*c) * 128 + l + 64]   = df.x;
        rp[(2*c+1) * 128 + l + 64] = df.y;
    }
}

// ---------------------------------------------------------------------------
// y pass: lines (x, kz) = L, elements at x*8320 + y*65 + kz.  1040 blocks.
// ---------------------------------------------------------------------------
template<int CONJ>
__global__ void k_fft_y() {
    __shared__ float2 bufA[8 * 129];
    __shared__ float2 bufB[8 * 129];
    __shared__ float2 tw[128];
    __shared__ int lineBase[8];
    int tid = threadIdx.x;
    init_tw(tw, tid);
    if (tid < 8) {
        int L = blockIdx.x * 8 + tid;
        int x = L / NZH, kz = L - x * NZH;
        lineBase[tid] = x * (128 * NZH) + kz;
    }
    __syncthreads();
    #pragma unroll
    for (int e = tid; e < 1024; e += 256) {
        int c = e & 7, l = e >> 3;
        bufA[sw(c * 129 + l)] = d_kmesh[lineBase[c] + l * NZH];
    }
    __syncthreads();
    fft_r4_stages<CONJ>(bufA, bufB, tw, tid);
    #pragma unroll
    for (int e = tid; e < 512; e += 256) {
        int c = e & 7, l = e >> 3;
        float2 a = bufB[sw(c * 129 + l)], b = bufB[sw(c * 129 + l + 64)];
        d_kmesh[lineBase[c] + l * NZH]        = cadd(a, b);
        d_kmesh[lineBase[c] + (l + 64) * NZH] = csub(a, b);
    }
}

// ---------------------------------------------------------------------------
// Fused x pass: fwd FFT along x, G(k)/V multiply, inv FFT along x. 1040 blocks.
// lines L = y*65 + kz, elements at x*8320 + L.
// ---------------------------------------------------------------------------
__global__ void k_fft_x_gmul(const float* __restrict__ cell) {
    __shared__ float2 bufA[8 * 129];
    __shared__ float2 bufB[8 * 129];
    __shared__ float2 tw[128];
    __shared__ float mjv[8], mkv[8];
    int tid = threadIdx.x;
    int L0 = blockIdx.x * 8;
    init_tw(tw, tid);
    if (tid < 8) {
        int L = L0 + tid;
        int y = L / NZH, kz = L - y * NZH;
        mjv[tid] = (float)(y - ((y >= 64) ? 128 : 0));
        mkv[tid] = (float)kz;
    }
    float inv[9]; float det;
    inv3x3(cell, inv, det);
    const float TWO_PI = 6.283185307179586f;
    float b0x = TWO_PI*inv[0], b0y = TWO_PI*inv[3], b0z = TWO_PI*inv[6];
    float b1x = TWO_PI*inv[1], b1y = TWO_PI*inv[4], b1z = TWO_PI*inv[7];
    float b2x = TWO_PI*inv[2], b2y = TWO_PI*inv[5], b2z = TWO_PI*inv[8];
    float ivol = 1.0f / fabsf(det);
    __syncthreads();
    #pragma unroll
    for (int e = tid; e < 1024; e += 256) {
        int c = e & 7, l = e >> 3;
        bufA[sw(c * 129 + l)] = d_kmesh[L0 + c + l * KLINES];
    }
    __syncthreads();
    fft_r4_stages<0>(bufA, bufB, tw, tid);
    r2_final_shared(bufB, bufA, tid);
    __syncthreads();
    // G(k)/V
    #pragma unroll
    for (int e = tid; e < 1024; e += 256) {
        int c = e >> 7, xk = e & 127;
        float mi = (float)(xk - ((xk >= 64) ? 128 : 0));
        float mj = mjv[c], mk = mkv[c];
        float kx = mi * b0x + mj * b1x + mk * b2x;
        float ky = mi * b0y + mj * b1y + mk * b2y;
        float kz = mi * b0z + mj * b1z + mk * b2z;
        float ksq = kx*kx + ky*ky + kz*kz;
        float g = 0.0f;
        if (ksq != 0.0f)
            g = 12.566370614359172f / ksq * expf(-0.5f * ksq) * ivol;
        float2 v = bufA[sw(c * 129 + xk)];
        v.x *= g; v.y *= g;
        bufA[sw(c * 129 + xk)] = v;
    }
    __syncthreads();
    fft_r4_stages<1>(bufA, bufB, tw, tid);
    #pragma unroll
    for (int e = tid; e < 512; e += 256) {
        int c = e & 7, l = e >> 3;
        float2 a = bufB[sw(c * 129 + l)], b = bufB[sw(c * 129 + l + 64)];
        d_kmesh[L0 + c + l * KLINES]        = cadd(a, b);
        d_kmesh[L0 + c + (l + 64) * KLINES] = csub(a, b);
    }
}

// ---------------------------------------------------------------------------
// spline weights + stencil
// ---------------------------------------------------------------------------
__device__ __forceinline__ void spline_w4(float x, float* w) {
    float x2 = x * x, x3 = x2 * x;
    const float s = 1.0f / 48.0f;
    w[0] = ( 1.0f -  6.0f*x + 12.0f*x2 -  8.0f*x3) * s;
    w[1] = (23.0f - 30.0f*x - 12.0f*x2 + 24.0f*x3) * s;
    w[2] = (23.0f + 30.0f*x - 12.0f*x2 - 24.0f*x3) * s;
    w[3] = ( 1.0f +  6.0f*x + 12.0f*x2 +  8.0f*x3) * s;
}

__device__ __forceinline__ int atom_stencil(
    const float* __restrict__ cell, const float* __restrict__ pos, int a,
    float* wx, float* wy, float* wz, int* ix, int* iy)
{
    float inv[9]; float det;
    inv3x3(cell, inv, det);
    float p0 = pos[3*a], p1 = pos[3*a+1], p2 = pos[3*a+2];
    float r0 = (p0*inv[0] + p1*inv[3] + p2*inv[6]) * 128.0f;
    float r1 = (p0*inv[1] + p1*inv[4] + p2*inv[7]) * 128.0f;
    float r2 = (p0*inv[2] + p1*inv[5] + p2*inv[8]) * 128.0f;
    int i0 = __float2int_rd(r0);
    int i1 = __float2int_rd(r1);
    int i2 = __float2int_rd(r2);
    spline_w4(r0 - (float)i0 - 0.5f, wx);
    spline_w4(r1 - (float)i1 - 0.5f, wy);
    spline_w4(r2 - (float)i2 - 0.5f, wz);
    #pragma unroll
    for (int s = 0; s < 4; s++) {
        ix[s] = (i0 + s - 1 + 128) & 127;
        iy[s] = (i1 + s - 1 + 128) & 127;
    }
    return i2;
}

__device__ __forceinline__ void pad_quads(const float* wz, int off,
                                          float* q0, float* q1) {
    switch (off) {
    case 0: q0[0]=wz[0]; q0[1]=wz[1]; q0[2]=wz[2]; q0[3]=wz[3]; break;
    case 1: q0[1]=wz[0]; q0[2]=wz[1]; q0[3]=wz[2]; q1[0]=wz[3]; break;
    case 2: q0[2]=wz[0]; q0[3]=wz[1]; q1[0]=wz[2]; q1[1]=wz[3]; break;
    default:q0[3]=wz[0]; q1[0]=wz[1]; q1[1]=wz[2]; q1[2]=wz[3]; break;
    }
}

__device__ __forceinline__ void red4(float* p, float a, float b, float c, float d) {
    asm volatile("red.global.add.v4.f32 [%0], {%1, %2, %3, %4};"
                 :: "l"(p), "f"(a), "f"(b), "f"(c), "f"(d) : "memory");
}
__device__ __forceinline__ void red2(float* p, float a, float b) {
    asm volatile("red.global.add.v2.f32 [%0], {%1, %2};"
                 :: "l"(p), "f"(a), "f"(b) : "memory");
}
__device__ __forceinline__ void red1(float* p, float a) {
    asm volatile("red.global.add.f32 [%0], %1;"
                 :: "l"(p), "f"(a) : "memory");
}

// ---------------------------------------------------------------------------
__global__ void k_scatter(const float* __restrict__ cell,
                          const float* __restrict__ pos,
                          const float* __restrict__ chg, int n) {
    int a = blockIdx.x * blockDim.x + threadIdx.x;
    if (a >= n) return;
    float wx[4], wy[4], wz[4];
    int ix[4], iy[4];
    int i2 = atom_stencil(cell, pos, a, wx, wy, wz, ix, iy);
    float c = chg[a];
    int zlo = i2 - 1;
    if (zlo >= 0 && zlo <= 124) {
        int Q0 = zlo & ~3, off = zlo & 3;
        #pragma unroll
        for (int i = 0; i < 4; i++) {
            float cwi = c * wx[i];
            int ox = ix[i] << 14;
            #pragma unroll
            for (int j = 0; j < 4; j++) {
                float s = cwi * wy[j];
                float* p = &d_rho[ox + (iy[j] << 7) + Q0];
                switch (off) {
                case 0:
                    red4(p, s*wz[0], s*wz[1], s*wz[2], s*wz[3]);
                    break;
                case 1:
                    red1(p + 1, s*wz[0]);
                    red2(p + 2, s*wz[1], s*wz[2]);
                    red1(p + 4, s*wz[3]);
                    break;
                case 2:
                    red2(p + 2, s*wz[0], s*wz[1]);
                    red2(p + 4, s*wz[2], s*wz[3]);
                    break;
                default:
                    red1(p + 3, s*wz[0]);
                    red2(p + 4, s*wz[1], s*wz[2]);
                    red1(p + 6, s*wz[3]);
                    break;
                }
            }
        }
    } else {
        int iz[4];
        #pragma unroll
        for (int s = 0; s < 4; s++) iz[s] = (zlo + s + 128) & 127;
        #pragma unroll
        for (int i = 0; i < 4; i++) {
            float cwi = c * wx[i];
            int ox = ix[i] << 14;
            #pragma unroll
            for (int j = 0; j < 4; j++) {
                float cwij = cwi * wy[j];
                int oxy = ox + (iy[j] << 7);
                #pragma unroll
                for (int k = 0; k < 4; k++)
                    red1(&d_rho[oxy + iz[k]], cwij * wz[k]);
            }
        }
    }
}

// ---------------------------------------------------------------------------
__global__ void k_gather(const float* __restrict__ cell,
                         const float* __restrict__ pos,
                         const float* __restrict__ chg,
                         float* __restrict__ out, int n) {
    int a = blockIdx.x * blockDim.x + threadIdx.x;
    if (a >= n) return;
    float wx[4], wy[4], wz[4];
    int ix[4], iy[4];
    int i2 = atom_stencil(cell, pos, a, wx, wy, wz, ix, iy);
    float sum = 0.0f;
    int zlo = i2 - 1;
    if (zlo >= 0 && zlo <= 124) {
        int Q0 = zlo & ~3, off = zlo & 3;
        float q0[4] = {0,0,0,0}, q1[4] = {0,0,0,0};
        pad_quads(wz, off, q0, q1);
        #pragma unroll
        for (int i = 0; i < 4; i++) {
            float wi = wx[i];
            int ox = ix[i] << 14;
            #pragma unroll
            for (int j = 0; j < 4; j++) {
                const float* p = &d_rho[ox + (iy[j] << 7) + Q0];
                float4 v0 = __ldg((const float4*)p);
                float acc = v0.x*q0[0] + v0.y*q0[1] + v0.z*q0[2] + v0.w*q0[3];
                if (off) {
                    float4 v1 = __ldg((const float4*)(p + 4));
                    acc += v1.x*q1[0] + v1.y*q1[1] + v1.z*q1[2] + v1.w*q1[3];
                }
                sum += wi * wy[j] * acc;
            }
        }
    } else {
        int iz[4];
        #pragma unroll
        for (int s = 0; s < 4; s++) iz[s] = (zlo + s + 128) & 127;
        #pragma unroll
        for (int i = 0; i < 4; i++) {
            float wi = wx[i];
            int ox = ix[i] << 14;
            #pragma unroll
            for (int j = 0; j < 4; j++) {
                int oxy = ox + (iy[j] << 7);
                float acc = 0.0f;
                #pragma unroll
                for (int k = 0; k < 4; k++)
                    acc += wz[k] * d_rho[oxy + iz[k]];
                sum += wi * wy[j] * acc;
            }
        }
    }
    out[a] = sum - chg[a] * 0.7978845608028654f;
}

// ---------------------------------------------------------------------------
extern "C" void kernel_launch(void* const* d_in, const int* in_sizes, int n_in,
                              void* d_out, int out_size) {
    const float* cell = (const float*)d_in[0];
    const float* pos  = (const float*)d_in[1];
    const float* chg  = (const float*)d_in[2];
    float* out = (float*)d_out;
    int n = in_sizes[2];

    k_zero<<<2048, 256>>>();

    int ab = (n + 255) / 256;
    k_scatter<<<ab, 256>>>(cell, pos, chg, n);

    k_fft_z_fwd<<<1024, 256>>>();
    k_fft_y<0><<<1040, 256>>>();
    k_fft_x_gmul<<<1040, 256>>>(cell);
    k_fft_y<1><<<1040, 256>>>();
    k_fft_z_inv<<<1024, 256>>>();

    k_gather<<<ab, 256>>>(cell, pos, chg, out, n);
}